// round 9
// baseline (speedup 1.0000x reference)
#include <cuda_runtime.h>
#include <cstdint>

typedef unsigned long long u64;
#define DEVINL __device__ __forceinline__

DEVINL u64 pack2(float lo, float hi) {
    u64 d;
    asm("mov.b64 %0, {%1, %2};" : "=l"(d) : "f"(lo), "f"(hi));
    return d;
}
DEVINL void unpack2(u64 v, float& lo, float& hi) {
    asm("mov.b64 {%0, %1}, %2;" : "=f"(lo), "=f"(hi) : "l"(v));
}
DEVINL u64 ffma2(u64 a, u64 b, u64 c) {
    u64 d;
    asm("fma.rn.f32x2 %0, %1, %2, %3;" : "=l"(d) : "l"(a), "l"(b), "l"(c));
    return d;
}

// smooth_leaky_relu(x) = 0.6x + 0.4x*tanh(x/2)   (alpha=0.2)
DEVINL float act_fn(float v) {
    float t;
    asm("tanh.approx.f32 %0, %1;" : "=f"(t) : "f"(0.5f * v));
    return v * (0.6f + 0.4f * t);
}

static constexpr int ROWLEN = 592;

// transposed weights, natural [k][o], packed back-to-back
__device__ float g_wt[21760];

__global__ void prep_kernel(const float* __restrict__ w0, const float* __restrict__ w1,
                            const float* __restrict__ w2, const float* __restrict__ w3) {
    int idx = blockIdx.x * 256 + threadIdx.x;
    if (idx < 16384) {
        int k = idx >> 7, o = idx & 127;
        g_wt[idx] = w0[o * 128 + k];
    } else if (idx < 20480) {
        int t = idx - 16384; int k = t >> 6, o = t & 63;
        g_wt[idx] = w1[o * 64 + k];
    } else if (idx < 21504) {
        int t = idx - 20480; int k = t >> 5, o = t & 31;
        g_wt[idx] = w2[o * 32 + k];
    } else if (idx < 21760) {
        int t = idx - 21504; int k = t >> 4, o = t & 15;
        g_wt[idx] = w3[o * 16 + k];
    }
}

// ===================== transpose-free scheme-0 kernel, W-phased =====================
// Xs / Os: NATURAL row-major [r][MUL*D], pitch P with P ≡ D (mod 32)  -> conflict-free.
// Ws: smem holds KCH = MUL/KPH weight rows at a time (phased for big W).
// Warps: OW output-groups (TO outputs each) x CW column-groups.
template<int MUL, int D, int R, int NW, int CW, int TO, int KPH,
         int IN_OFF, int WOFF, bool ACT, int MINB>
__global__ __launch_bounds__(NW * 32, MINB)
void seg_s0(const float* __restrict__ x, const float* __restrict__ bias,
            float* __restrict__ out, int N) {
    constexpr int NT     = NW * 32;
    constexpr int K      = MUL;
    constexpr int KCH    = K / KPH;
    constexpr int SEGLEN = MUL * D;
    constexpr int SEGF4  = SEGLEN / 4;
    constexpr int CBLK   = R * D;
    constexpr int OW     = NW / CW;
    constexpr int CPW    = CBLK / CW;
    constexpr int TC     = CPW / 32;
    constexpr int TOH    = TO / 2;
    constexpr int TOQ    = TO / 4;
    constexpr int P      = SEGLEN + ((32 + D - (SEGLEN % 32)) % 32);
    static_assert(OW * TO == MUL, "");
    static_assert(CPW % 32 == 0, "");
    static_assert(TO % 4 == 0, "");
    static_assert(P % 32 == D % 32, "");

    extern __shared__ float smem[];
    float* Ws = smem;                   // KCH*MUL (current W phase)
    float* Xs = smem + KCH * MUL;       // [r][P] natural
    float* Os = Xs;                     // alias after GEMM

    const int tid = threadIdx.x, lane = tid & 31, warp = tid >> 5;
    const int r0 = blockIdx.x * R;
    const int nrows = min(R, N - r0);
    const int ob = (warp % OW) * TO;
    const int cbase = (warp / OW) * CPW + lane;

    // ---- X load: natural copy, scalar STS (conflict-free; P odd) ----
    const int nld = nrows * SEGF4;
    #pragma unroll 1
    for (int i = tid; i < nld; i += NT) {
        int r = i / SEGF4, q = i - r * SEGF4;
        float4 v = *(const float4*)(x + (size_t)(r0 + r) * ROWLEN + IN_OFF + 4 * q);
        float* dst = Xs + r * P + 4 * q;
        dst[0] = v.x; dst[1] = v.y; dst[2] = v.z; dst[3] = v.w;
    }

    int bx[TC];
    #pragma unroll
    for (int i = 0; i < TC; i++) {
        int c = cbase + 32 * i;
        bx[i] = (c / D) * P + (c % D);
    }

    u64 acc[TC][TOH];
    #pragma unroll
    for (int p = 0; p < TOH; p++) {
        u64 bp = pack2(__ldg(bias + ob + 2 * p), __ldg(bias + ob + 2 * p + 1));
        #pragma unroll
        for (int i = 0; i < TC; i++) acc[i][p] = bp;
    }

    #pragma unroll
    for (int ph = 0; ph < KPH; ph++) {
        if (ph) __syncthreads();        // previous GEMM done reading Ws
        // ---- load this phase's W rows ----
        #pragma unroll 1
        for (int i = tid; i < KCH * MUL / 4; i += NT)
            ((float4*)Ws)[i] = ((const float4*)(g_wt + WOFF + ph * KCH * MUL))[i];
        __syncthreads();                // W ready (also X ready when ph==0)

        // ---- GEMM over this phase ----
        #pragma unroll 8
        for (int kl = 0; kl < KCH; kl++) {
            int k = ph * KCH + kl;
            u64 xd[TC];
            #pragma unroll
            for (int i = 0; i < TC; i++) {
                float xv = Xs[bx[i] + k * D];
                xd[i] = pack2(xv, xv);
            }
            const ulonglong2* wq = (const ulonglong2*)(Ws + kl * MUL + ob);
            #pragma unroll
            for (int j = 0; j < TOQ; j++) {
                ulonglong2 w2 = wq[j];
                #pragma unroll
                for (int i = 0; i < TC; i++) {
                    acc[i][2 * j]     = ffma2(xd[i], w2.x, acc[i][2 * j]);
                    acc[i][2 * j + 1] = ffma2(xd[i], w2.y, acc[i][2 * j + 1]);
                }
            }
        }
    }
    __syncthreads();

    // ---- stage accumulators into natural Os (banks ≡ c + D*o: conflict-free) ----
    #pragma unroll
    for (int i = 0; i < TC; i++) {
        int c = cbase + 32 * i;
        float* od = Os + (c / D) * P + (c % D);
        #pragma unroll
        for (int p = 0; p < TOH; p++) {
            float lo, hi; unpack2(acc[i][p], lo, hi);
            od[(ob + 2 * p) * D]     = lo;
            od[(ob + 2 * p + 1) * D] = hi;
        }
    }
    __syncthreads();

    // ---- epilogue: natural-order scalar LDS, coalesced float4 STG ----
    #pragma unroll 1
    for (int i = tid; i < nld; i += NT) {
        int r = i / SEGF4, q = i - r * SEGF4;
        const float* src = Os + r * P + 4 * q;
        float4 v;
        if (ACT) {
            v.x = act_fn(src[0]); v.y = act_fn(src[1]);
            v.z = act_fn(src[2]); v.w = act_fn(src[3]);
        } else {
            v.x = src[0]; v.y = src[1]; v.z = src[2]; v.w = src[3];
        }
        *(float4*)(out + (size_t)(r0 + r) * ROWLEN + IN_OFF + 4 * q) = v;
    }
}

constexpr int pitch_of(int seglen, int d) {
    return seglen + ((32 + d - (seglen % 32)) % 32);
}

// ---- streams/events for fork-join overlap inside the captured graph ----
static cudaStream_t g_side[3];
static cudaEvent_t  g_ev_root;
static cudaEvent_t  g_ev_done[3];
static bool         g_init_done = false;

extern "C" void kernel_launch(void* const* d_in, const int* in_sizes, int n_in,
                              void* d_out, int out_size) {
    const float* x  = (const float*)d_in[0];
    const float* w0 = (const float*)d_in[1];
    const float* w1 = (const float*)d_in[2];
    const float* w2 = (const float*)d_in[3];
    const float* w3 = (const float*)d_in[4];
    const float* b0 = (const float*)d_in[5];
    const float* b1 = (const float*)d_in[6];
    const float* b2 = (const float*)d_in[7];
    const float* b3 = (const float*)d_in[8];
    float* out = (float*)d_out;
    const int N = in_sizes[0] / ROWLEN;

    if (!g_init_done) {
        for (int i = 0; i < 3; i++)
            cudaStreamCreateWithFlags(&g_side[i], cudaStreamNonBlocking);
        cudaEventCreateWithFlags(&g_ev_root, cudaEventDisableTiming);
        for (int i = 0; i < 3; i++)
            cudaEventCreateWithFlags(&g_ev_done[i], cudaEventDisableTiming);
        g_init_done = true;
    }

    //              MUL  D   R NW CW  TO KPH IN_OFF  WOFF   ACT  MINB
    auto k0 = seg_s0<128, 1, 32, 8, 1, 16, 2,     0,     0,  true, 4>;
    auto k1 = seg_s0< 64, 3, 32, 8, 1,  8, 1,   128, 16384, false, 4>;
    auto k2 = seg_s0< 32, 5, 32, 8, 1,  4, 1,   320, 20480, false, 4>;
    auto k3 = seg_s0< 16, 7, 32, 4, 1,  4, 1,   480, 21504, false, 8>;

    // smem bytes: (KCH*MUL + R*P) * 4
    constexpr int S0 = (64 * 128 + 32 * pitch_of(128, 1)) * 4;   // (8192+4128)*4 = 49280
    constexpr int S1 = (64 * 64  + 32 * pitch_of(192, 3)) * 4;   // (4096+6240)*4 = 41344
    constexpr int S2 = (32 * 32  + 32 * pitch_of(160, 5)) * 4;   // (1024+5280)*4 = 25216
    constexpr int S3 = (16 * 16  + 32 * pitch_of(112, 7)) * 4;   // (256 +4320)*4 = 18304

    cudaFuncSetAttribute(k0, cudaFuncAttributeMaxDynamicSharedMemorySize, S0);
    cudaFuncSetAttribute(k1, cudaFuncAttributeMaxDynamicSharedMemorySize, S1);
    cudaFuncSetAttribute(k2, cudaFuncAttributeMaxDynamicSharedMemorySize, S2);
    cudaFuncSetAttribute(k3, cudaFuncAttributeMaxDynamicSharedMemorySize, S3);

    // ---- fork: prep on main stream, segs 1..3 on side streams ----
    prep_kernel<<<85, 256>>>(w0, w1, w2, w3);
    cudaEventRecord(g_ev_root, 0);
    for (int i = 0; i < 3; i++)
        cudaStreamWaitEvent(g_side[i], g_ev_root, 0);

    const int g32 = (N + 31) / 32;   // 3125

    k0<<<g32, 256, S0>>>(x, b0, out, N);                 // main stream
    k1<<<g32, 256, S1, g_side[0]>>>(x, b1, out, N);
    k2<<<g32, 256, S2, g_side[1]>>>(x, b2, out, N);
    k3<<<g32, 128, S3, g_side[2]>>>(x, b3, out, N);

    // ---- join back onto the main (capture) stream ----
    for (int i = 0; i < 3; i++) {
        cudaEventRecord(g_ev_done[i], g_side[i]);
        cudaStreamWaitEvent(0, g_ev_done[i], 0);
    }
}

// round 12
// speedup vs baseline: 1.2546x; 1.2546x over previous
#include <cuda_runtime.h>
#include <cuda_bf16.h>
#include <mma.h>
#include <cstdint>

using namespace nvcuda;

typedef unsigned long long u64;
#define DEVINL __device__ __forceinline__

DEVINL u64 pack2(float lo, float hi) {
    u64 d;
    asm("mov.b64 %0, {%1, %2};" : "=l"(d) : "f"(lo), "f"(hi));
    return d;
}
DEVINL void unpack2(u64 v, float& lo, float& hi) {
    asm("mov.b64 {%0, %1}, %2;" : "=f"(lo), "=f"(hi) : "l"(v));
}
DEVINL u64 ffma2(u64 a, u64 b, u64 c) {
    u64 d;
    asm("fma.rn.f32x2 %0, %1, %2, %3;" : "=l"(d) : "l"(a), "l"(b), "l"(c));
    return d;
}

// smooth_leaky_relu(x) = 0.6x + 0.4x*tanh(x/2)   (alpha=0.2)
DEVINL float act_fn(float v) {
    float t;
    asm("tanh.approx.f32 %0, %1;" : "=f"(t) : "f"(0.5f * v));
    return v * (0.6f + 0.4f * t);
}

static constexpr int ROWLEN = 592;

// single extern shared symbol, consistent type everywhere
extern __shared__ float smem[];

// ===================== weights scratch =====================
// g_wt: transposed fp32 [k][o] for segments 1-3
__device__ float g_wt[21760];
// seg0 W0 as bf16 hi/lo, natural [o][k] layout
__device__ __nv_bfloat16 g_w0hi[16384];
__device__ __nv_bfloat16 g_w0lo[16384];

__global__ void prep_kernel(const float* __restrict__ w1, const float* __restrict__ w2,
                            const float* __restrict__ w3) {
    int idx = blockIdx.x * 256 + threadIdx.x + 16384;
    if (idx < 20480) {
        int t = idx - 16384; int k = t >> 6, o = t & 63;
        g_wt[idx] = w1[o * 64 + k];
    } else if (idx < 21504) {
        int t = idx - 20480; int k = t >> 5, o = t & 31;
        g_wt[idx] = w2[o * 32 + k];
    } else if (idx < 21760) {
        int t = idx - 21504; int k = t >> 4, o = t & 15;
        g_wt[idx] = w3[o * 16 + k];
    }
}

__global__ void prep_w0(const float* __restrict__ w0) {
    int idx = blockIdx.x * 256 + threadIdx.x;
    if (idx >= 16384) return;
    float w = w0[idx];                       // natural [o][k]
    __nv_bfloat16 h = __float2bfloat16(w);
    float l = w - __bfloat162float(h);
    g_w0hi[idx] = h;
    g_w0lo[idx] = __float2bfloat16(l);
}

// ===================== seg0: wmma bf16-split GEMM =====================
// C[128 rows, 128 o] = X[128,128] @ W0^T  (+b0, act)
// bf16 split: hi*hi + hi*lo + lo*hi (lo*lo dropped). K in 2 chunks of 64.
// 8 warps, warp tile 64(rows) x 32(o) = 4x2 wmma 16x16x16 tiles.
static constexpr int LDA0 = 72;     // bf16 pitch for A/W chunk tiles (64 + 8 pad)
static constexpr int LDO0 = 132;    // float pitch for output staging
// float offsets in smem
static constexpr int F_BIAS = 0;                    // 128 floats
static constexpr int F_AHI  = 128;                  // 128*72/2 = 4608 floats each
static constexpr int F_ALO  = F_AHI + 4608;
static constexpr int F_WHI  = F_ALO + 4608;
static constexpr int F_WLO  = F_WHI + 4608;
static constexpr int SM0_BYTES = (F_WLO + 4608) * 4;   // 74240 bytes

__global__ __launch_bounds__(256, 2)
void seg0_wmma(const float* __restrict__ x, const float* __restrict__ b0,
               float* __restrict__ out, int N) {
    const int tid = threadIdx.x, warp = tid >> 5;
    const int r0 = blockIdx.x * 128;

    __nv_bfloat16* sAh = (__nv_bfloat16*)(smem + F_AHI);
    __nv_bfloat16* sAl = (__nv_bfloat16*)(smem + F_ALO);
    __nv_bfloat16* sWh = (__nv_bfloat16*)(smem + F_WHI);
    __nv_bfloat16* sWl = (__nv_bfloat16*)(smem + F_WLO);

    if (tid < 128) smem[F_BIAS + tid] = b0[tid];

    const int wrow = (warp >> 2) * 64;   // 0 or 64
    const int wcol = (warp & 3) * 32;    // 0,32,64,96

    wmma::fragment<wmma::accumulator, 16, 16, 16, float> acc[4][2];
    #pragma unroll
    for (int m = 0; m < 4; m++)
        #pragma unroll
        for (int n = 0; n < 2; n++)
            wmma::fill_fragment(acc[m][n], 0.0f);

    #pragma unroll 1
    for (int c = 0; c < 2; c++) {
        __syncthreads();   // previous chunk's GEMM reads done (and bias store on c=0)

        // ---- stage A chunk: 128 rows x 64 k, bf16 hi/lo split ----
        #pragma unroll 1
        for (int i = tid; i < 128 * 16; i += 256) {
            int row = i >> 4, q = i & 15;
            float4 v = make_float4(0.f, 0.f, 0.f, 0.f);
            if (r0 + row < N)
                v = *(const float4*)(x + (size_t)(r0 + row) * ROWLEN + 64 * c + 4 * q);
            __nv_bfloat16 h0 = __float2bfloat16(v.x), h1 = __float2bfloat16(v.y);
            __nv_bfloat16 h2 = __float2bfloat16(v.z), h3 = __float2bfloat16(v.w);
            float l0 = v.x - __bfloat162float(h0), l1 = v.y - __bfloat162float(h1);
            float l2 = v.z - __bfloat162float(h2), l3 = v.w - __bfloat162float(h3);
            __nv_bfloat162 hp0 = __halves2bfloat162(h0, h1);
            __nv_bfloat162 hp1 = __halves2bfloat162(h2, h3);
            __nv_bfloat162 lp0 = __floats2bfloat162_rn(l0, l1);
            __nv_bfloat162 lp1 = __floats2bfloat162_rn(l2, l3);
            uint2 uh; uh.x = *(uint32_t*)&hp0; uh.y = *(uint32_t*)&hp1;
            uint2 ul; ul.x = *(uint32_t*)&lp0; ul.y = *(uint32_t*)&lp1;
            *(uint2*)(sAh + row * LDA0 + 4 * q) = uh;
            *(uint2*)(sAl + row * LDA0 + 4 * q) = ul;
        }
        // ---- stage W chunk: 128 o x 64 k (pre-split bf16, natural [o][k]) ----
        #pragma unroll 1
        for (int i = tid; i < 128 * 8; i += 256) {
            int o = i >> 3, q = i & 7;
            *(uint4*)(sWh + o * LDA0 + 8 * q) = *(const uint4*)(g_w0hi + o * 128 + 64 * c + 8 * q);
            *(uint4*)(sWl + o * LDA0 + 8 * q) = *(const uint4*)(g_w0lo + o * 128 + 64 * c + 8 * q);
        }
        __syncthreads();

        // ---- GEMM: 4 k-steps of 16 ----
        #pragma unroll
        for (int ks = 0; ks < 4; ks++) {
            wmma::fragment<wmma::matrix_b, 16, 16, 16, __nv_bfloat16, wmma::col_major> bh[2], bl[2];
            #pragma unroll
            for (int n = 0; n < 2; n++) {
                wmma::load_matrix_sync(bh[n], sWh + (wcol + 16 * n) * LDA0 + 16 * ks, LDA0);
                wmma::load_matrix_sync(bl[n], sWl + (wcol + 16 * n) * LDA0 + 16 * ks, LDA0);
            }
            #pragma unroll
            for (int m = 0; m < 4; m++) {
                wmma::fragment<wmma::matrix_a, 16, 16, 16, __nv_bfloat16, wmma::row_major> ah, al;
                wmma::load_matrix_sync(ah, sAh + (wrow + 16 * m) * LDA0 + 16 * ks, LDA0);
                wmma::load_matrix_sync(al, sAl + (wrow + 16 * m) * LDA0 + 16 * ks, LDA0);
                #pragma unroll
                for (int n = 0; n < 2; n++) {
                    wmma::mma_sync(acc[m][n], ah, bh[n], acc[m][n]);
                    wmma::mma_sync(acc[m][n], ah, bl[n], acc[m][n]);
                    wmma::mma_sync(acc[m][n], al, bh[n], acc[m][n]);
                }
            }
        }
    }
    __syncthreads();   // GEMM reads done; Os may overwrite A area

    // ---- stage result to smem (row-major, pitch LDO0) ----
    float* Os = smem + F_AHI;   // 128*132 = 16896 floats fits in A-hi/lo area (9216*... ok)
    #pragma unroll
    for (int m = 0; m < 4; m++)
        #pragma unroll
        for (int n = 0; n < 2; n++)
            wmma::store_matrix_sync(Os + (wrow + 16 * m) * LDO0 + wcol + 16 * n,
                                    acc[m][n], LDO0, wmma::mem_row_major);
    __syncthreads();

    // ---- epilogue: bias + act, coalesced float4 out ----
    const float* bias_s = smem + F_BIAS;
    #pragma unroll 1
    for (int i = tid; i < 128 * 32; i += 256) {
        int row = i >> 5, q = i & 31;
        if (r0 + row < N) {
            const float* src = Os + row * LDO0 + 4 * q;
            float4 v;
            v.x = act_fn(src[0] + bias_s[4 * q + 0]);
            v.y = act_fn(src[1] + bias_s[4 * q + 1]);
            v.z = act_fn(src[2] + bias_s[4 * q + 2]);
            v.w = act_fn(src[3] + bias_s[4 * q + 3]);
            *(float4*)(out + (size_t)(r0 + row) * ROWLEN + 4 * q) = v;
        }
    }
}

// ===================== FFMA2 kernels for segs 1-3 (R9, unchanged) =====================
template<int MUL, int D, int R, int NW, int CW, int TO, int KPH,
         int IN_OFF, int WOFF, bool ACT, int MINB>
__global__ __launch_bounds__(NW * 32, MINB)
void seg_s0(const float* __restrict__ x, const float* __restrict__ bias,
            float* __restrict__ out, int N) {
    constexpr int NT     = NW * 32;
    constexpr int K      = MUL;
    constexpr int KCH    = K / KPH;
    constexpr int SEGLEN = MUL * D;
    constexpr int SEGF4  = SEGLEN / 4;
    constexpr int CBLK   = R * D;
    constexpr int OW     = NW / CW;
    constexpr int CPW    = CBLK / CW;
    constexpr int TC     = CPW / 32;
    constexpr int TOH    = TO / 2;
    constexpr int TOQ    = TO / 4;
    constexpr int P      = SEGLEN + ((32 + D - (SEGLEN % 32)) % 32);
    static_assert(OW * TO == MUL, "");
    static_assert(CPW % 32 == 0, "");
    static_assert(TO % 4 == 0, "");
    static_assert(P % 32 == D % 32, "");

    float* Ws = smem;
    float* Xs = smem + KCH * MUL;
    float* Os = Xs;

    const int tid = threadIdx.x, lane = tid & 31, warp = tid >> 5;
    const int r0 = blockIdx.x * R;
    const int nrows = min(R, N - r0);
    const int ob = (warp % OW) * TO;
    const int cbase = (warp / OW) * CPW + lane;

    const int nld = nrows * SEGF4;
    #pragma unroll 1
    for (int i = tid; i < nld; i += NT) {
        int r = i / SEGF4, q = i - r * SEGF4;
        float4 v = *(const float4*)(x + (size_t)(r0 + r) * ROWLEN + IN_OFF + 4 * q);
        float* dst = Xs + r * P + 4 * q;
        dst[0] = v.x; dst[1] = v.y; dst[2] = v.z; dst[3] = v.w;
    }

    int bx[TC];
    #pragma unroll
    for (int i = 0; i < TC; i++) {
        int c = cbase + 32 * i;
        bx[i] = (c / D) * P + (c % D);
    }

    u64 acc[TC][TOH];
    #pragma unroll
    for (int p = 0; p < TOH; p++) {
        u64 bp = pack2(__ldg(bias + ob + 2 * p), __ldg(bias + ob + 2 * p + 1));
        #pragma unroll
        for (int i = 0; i < TC; i++) acc[i][p] = bp;
    }

    #pragma unroll
    for (int ph = 0; ph < KPH; ph++) {
        if (ph) __syncthreads();
        #pragma unroll 1
        for (int i = tid; i < KCH * MUL / 4; i += NT)
            ((float4*)Ws)[i] = ((const float4*)(g_wt + WOFF + ph * KCH * MUL))[i];
        __syncthreads();

        #pragma unroll 8
        for (int kl = 0; kl < KCH; kl++) {
            int k = ph * KCH + kl;
            u64 xd[TC];
            #pragma unroll
            for (int i = 0; i < TC; i++) {
                float xv = Xs[bx[i] + k * D];
                xd[i] = pack2(xv, xv);
            }
            const ulonglong2* wq = (const ulonglong2*)(Ws + kl * MUL + ob);
            #pragma unroll
            for (int j = 0; j < TOQ; j++) {
                ulonglong2 w2 = wq[j];
                #pragma unroll
                for (int i = 0; i < TC; i++) {
                    acc[i][2 * j]     = ffma2(xd[i], w2.x, acc[i][2 * j]);
                    acc[i][2 * j + 1] = ffma2(xd[i], w2.y, acc[i][2 * j + 1]);
                }
            }
        }
    }
    __syncthreads();

    #pragma unroll
    for (int i = 0; i < TC; i++) {
        int c = cbase + 32 * i;
        float* od = Os + (c / D) * P + (c % D);
        #pragma unroll
        for (int p = 0; p < TOH; p++) {
            float lo, hi; unpack2(acc[i][p], lo, hi);
            od[(ob + 2 * p) * D]     = lo;
            od[(ob + 2 * p + 1) * D] = hi;
        }
    }
    __syncthreads();

    #pragma unroll 1
    for (int i = tid; i < nld; i += NT) {
        int r = i / SEGF4, q = i - r * SEGF4;
        const float* src = Os + r * P + 4 * q;
        float4 v;
        if (ACT) {
            v.x = act_fn(src[0]); v.y = act_fn(src[1]);
            v.z = act_fn(src[2]); v.w = act_fn(src[3]);
        } else {
            v.x = src[0]; v.y = src[1]; v.z = src[2]; v.w = src[3];
        }
        *(float4*)(out + (size_t)(r0 + r) * ROWLEN + IN_OFF + 4 * q) = v;
    }
}

constexpr int pitch_of(int seglen, int d) {
    return seglen + ((32 + d - (seglen % 32)) % 32);
}

// ---- streams/events for fork-join overlap inside the captured graph ----
static cudaStream_t g_side[3];
static cudaEvent_t  g_ev_root;
static cudaEvent_t  g_ev_done[3];
static bool         g_init_done = false;

extern "C" void kernel_launch(void* const* d_in, const int* in_sizes, int n_in,
                              void* d_out, int out_size) {
    const float* x  = (const float*)d_in[0];
    const float* w0 = (const float*)d_in[1];
    const float* w1 = (const float*)d_in[2];
    const float* w2 = (const float*)d_in[3];
    const float* w3 = (const float*)d_in[4];
    const float* b0 = (const float*)d_in[5];
    const float* b1 = (const float*)d_in[6];
    const float* b2 = (const float*)d_in[7];
    const float* b3 = (const float*)d_in[8];
    float* out = (float*)d_out;
    const int N = in_sizes[0] / ROWLEN;

    if (!g_init_done) {
        for (int i = 0; i < 3; i++)
            cudaStreamCreateWithFlags(&g_side[i], cudaStreamNonBlocking);
        cudaEventCreateWithFlags(&g_ev_root, cudaEventDisableTiming);
        for (int i = 0; i < 3; i++)
            cudaEventCreateWithFlags(&g_ev_done[i], cudaEventDisableTiming);
        g_init_done = true;
    }

    //              MUL  D   R NW CW  TO KPH IN_OFF  WOFF   ACT  MINB
    auto k1 = seg_s0< 64, 3, 32, 8, 1,  8, 1,   128, 16384, false, 4>;
    auto k2 = seg_s0< 32, 5, 32, 8, 1,  4, 1,   320, 20480, false, 4>;
    auto k3 = seg_s0< 16, 7, 32, 4, 1,  4, 1,   480, 21504, false, 8>;

    constexpr int S1 = (64 * 64 + 32 * pitch_of(192, 3)) * 4;   // 41344
    constexpr int S2 = (32 * 32 + 32 * pitch_of(160, 5)) * 4;   // 25216
    constexpr int S3 = (16 * 16 + 32 * pitch_of(112, 7)) * 4;   // 18304

    cudaFuncSetAttribute(seg0_wmma, cudaFuncAttributeMaxDynamicSharedMemorySize, SM0_BYTES);
    cudaFuncSetAttribute(k1, cudaFuncAttributeMaxDynamicSharedMemorySize, S1);
    cudaFuncSetAttribute(k2, cudaFuncAttributeMaxDynamicSharedMemorySize, S2);
    cudaFuncSetAttribute(k3, cudaFuncAttributeMaxDynamicSharedMemorySize, S3);

    // ---- prep on main stream, then fork ----
    prep_kernel<<<21, 256>>>(w1, w2, w3);
    prep_w0<<<64, 256>>>(w0);
    cudaEventRecord(g_ev_root, 0);
    for (int i = 0; i < 3; i++)
        cudaStreamWaitEvent(g_side[i], g_ev_root, 0);

    const int g128 = (N + 127) / 128;   // 782
    const int g32  = (N + 31) / 32;     // 3125

    seg0_wmma<<<g128, 256, SM0_BYTES>>>(x, b0, out, N);    // main stream (tensor pipe)
    k1<<<g32, 256, S1, g_side[0]>>>(x, b1, out, N);
    k2<<<g32, 256, S2, g_side[1]>>>(x, b2, out, N);
    k3<<<g32, 128, S3, g_side[2]>>>(x, b3, out, N);

    // ---- join back onto the main (capture) stream ----
    for (int i = 0; i < 3; i++) {
        cudaEventRecord(g_ev_done[i], g_side[i]);
        cudaStreamWaitEvent(0, g_ev_done[i], 0);
    }
}